// round 15
// baseline (speedup 1.0000x reference)
#include <cuda_runtime.h>
#include <cuda_bf16.h>

// Problem constants
#define BATCH 128
#define BINS 128
#define HW 262144               // 512*512 elements per batch (C=1)
#define TOTAL (BATCH * HW)      // 33554432
#define HIST_BPB 16             // histogram blocks per batch
#define HIST_THREADS 256
#define CHUNK (HW / HIST_BPB)   // 16384 elements per hist block
#define SCALE_BPB 4             // scale blocks per batch
#define SCALE_NBLK (BATCH * SCALE_BPB)
#define SCHUNK (HW / SCALE_BPB) // 65536 elements per scale block

// Scratch (device globals: no allocations allowed)
__device__ float g_part[HIST_BPB * BATCH * BINS];   // [part][batch][bin]

// 32-byte (8-float) global load with L2 evict_last policy (sm_103a requires
// .v8.b32/.v4.b64 for this modifier).
struct F8 { float f[8]; };
static __device__ __forceinline__ F8 ldg32_evict_last(const void* p) {
    unsigned long long a, b, c, d;
    asm volatile("ld.global.L2::evict_last.v4.b64 {%0,%1,%2,%3}, [%4];"
                 : "=l"(a), "=l"(b), "=l"(c), "=l"(d)
                 : "l"(p));
    F8 r;
    r.f[0] = __uint_as_float((unsigned)(a));  r.f[1] = __uint_as_float((unsigned)(a >> 32));
    r.f[2] = __uint_as_float((unsigned)(b));  r.f[3] = __uint_as_float((unsigned)(b >> 32));
    r.f[4] = __uint_as_float((unsigned)(c));  r.f[5] = __uint_as_float((unsigned)(c >> 32));
    r.f[6] = __uint_as_float((unsigned)(d));  r.f[7] = __uint_as_float((unsigned)(d >> 32));
    return r;
}

// ---------------------------------------------------------------------------
// Kernel 1: per-batch histogram (measured 29.5us in R10).
// 256 threads/block, per-thread private UINT8 counters, 32 KB smem.
// Conflict-free: counter(bin,t) at byte bin*256 + (t&31)*4 + ((t>>5)&3)
//   + (t>>7)*128  -> word bank = t&31, independent of bin.
// 64 elements/thread -> uint8 cannot overflow.
// ---------------------------------------------------------------------------
__global__ void __launch_bounds__(HIST_THREADS) hist_kernel(const float* __restrict__ x) {
    __shared__ unsigned char sh[BINS * 256];             // 32 KB
    unsigned int* sh32 = reinterpret_cast<unsigned int*>(sh);

    const int t = threadIdx.x;

    // zero: 8192 words / 256 threads = 32 each, bank = t&31: conflict-free
    #pragma unroll
    for (int i = 0; i < 32; i++)
        sh32[i * 256 + t] = 0u;
    __syncthreads();

    const int batch = blockIdx.x >> 4;              // / HIST_BPB
    const int part  = blockIdx.x & (HIST_BPB - 1);
    const int lane_off = (t & 31) * 4 + ((t >> 5) & 3) + (t >> 7) * 128;

    const char* xp = reinterpret_cast<const char*>(x)
                   + ((size_t)batch * HW + (size_t)part * CHUNK) * 4;

    // CHUNK/8 = 2048 8-float groups per block, 256 threads -> 8 iterations
    #pragma unroll 8
    for (int i = t; i < CHUNK / 8; i += HIST_THREADS) {
        F8 v = ldg32_evict_last(xp + (size_t)i * 32);
        #pragma unroll
        for (int e = 0; e < 8; e++) {
            float g = v.f[e] * 128.0f;               // exact (x * 2^7)
            int bin = min(__float2int_rd(g), BINS - 1);
            if (g >= 0.0f && g <= 128.0f) sh[bin * 256 + lane_off]++;
        }
    }
    __syncthreads();

    // Reduce: thread t (t<128) sums bin t's 256 counters = 64 words x 4 bytes
    // (dp4a). Rotated read j=(t+i)&63 -> conflict-free.
    if (t < BINS) {
        unsigned int s = 0;
        #pragma unroll
        for (int i = 0; i < 64; i++) {
            int j = (t + i) & 63;
            s = __dp4a(sh32[t * 64 + j], 0x01010101u, s);
        }
        g_part[(part * BATCH + batch) * BINS + t] = (float)s;
    }
}

// ---------------------------------------------------------------------------
// Kernel 2: fused MLP + scale. 512 blocks (4 per batch) x 256 threads.
// Each block redundantly computes w for ITS batch (16 coalesced g_part loads
// per thread + shfl/smem reduction: ~2us latency, overlapped across blocks),
// then scales its 256 KB chunk. Removes the separate mlp launch + kernel gap.
// Reversed block order + __ldcs/__stcs: exploit x still resident in L2 from
// the hist pass (verified -4us in R8).
// ---------------------------------------------------------------------------
__global__ void __launch_bounds__(256) mlp_scale_kernel(const float* __restrict__ W1,
                                                        const float* __restrict__ b1,
                                                        const float* __restrict__ W2,
                                                        const float* __restrict__ b2,
                                                        const float* __restrict__ x,
                                                        float* __restrict__ out) {
    const int blk   = gridDim.x - 1 - blockIdx.x;   // reversed: hot tail first
    const int batch = blk >> 2;                     // / SCALE_BPB
    const int part  = blk & (SCALE_BPB - 1);

    const int t = threadIdx.x;
    const int lane = t & 31;
    const int warp = t >> 5;

    __shared__ float sh_h[4][16];
    __shared__ float s_w;

    // ---- MLP for own batch ----
    float hp[16];
    if (t < BINS) {
        float c = 0.0f;
        #pragma unroll
        for (int p = 0; p < HIST_BPB; p++)
            c += g_part[(p * BATCH + batch) * BINS + t];
        #pragma unroll
        for (int j = 0; j < 16; j++)
            hp[j] = c * W1[t * 16 + j];
    } else {
        #pragma unroll
        for (int j = 0; j < 16; j++) hp[j] = 0.0f;
    }
    if (warp < 4) {
        #pragma unroll
        for (int j = 0; j < 16; j++) {
            #pragma unroll
            for (int off = 16; off >= 1; off >>= 1)
                hp[j] += __shfl_xor_sync(0xFFFFFFFFu, hp[j], off);
        }
        if (lane == 0) {
            #pragma unroll
            for (int j = 0; j < 16; j++)
                sh_h[warp][j] = hp[j];
        }
    }
    __syncthreads();
    if (t < 32) {
        float v = 0.0f;
        if (t < 16) {
            float h = sh_h[0][t] + sh_h[1][t] + sh_h[2][t] + sh_h[3][t] + b1[t];
            v = fmaxf(h, 0.0f) * W2[t];
        }
        #pragma unroll
        for (int off = 8; off >= 1; off >>= 1)
            v += __shfl_xor_sync(0xFFFFFFFFu, v, off);
        if (t == 0)
            s_w = v + b2[0];
    }
    __syncthreads();
    const float w = s_w;

    // ---- scale own chunk ----
    const float4* xin = reinterpret_cast<const float4*>(x)
                      + (size_t)batch * (HW / 4) + (size_t)part * (SCHUNK / 4);
    float4* op = reinterpret_cast<float4*>(out)
               + (size_t)batch * (HW / 4) + (size_t)part * (SCHUNK / 4);
    // SCHUNK/4 = 16384 float4, 256 threads -> 64 iterations
    #pragma unroll 4
    for (int i = t; i < SCHUNK / 4; i += 256) {
        float4 v = __ldcs(xin + i);                 // dead after this read
        v.x *= w; v.y *= w; v.z *= w; v.w *= w;
        __stcs(op + i, v);                          // don't pollute L2
    }
}

// ---------------------------------------------------------------------------
// Launch: two kernels (no grid barrier, no deadlock surface).
// ---------------------------------------------------------------------------
extern "C" void kernel_launch(void* const* d_in, const int* in_sizes, int n_in,
                              void* d_out, int out_size) {
    const float* x  = (const float*)d_in[0];
    const float* W1 = (const float*)d_in[1];
    const float* b1 = (const float*)d_in[2];
    const float* W2 = (const float*)d_in[3];
    const float* b2 = (const float*)d_in[4];
    float* out = (float*)d_out;

    hist_kernel<<<BATCH * HIST_BPB, HIST_THREADS>>>(x);
    mlp_scale_kernel<<<SCALE_NBLK, 256>>>(W1, b1, W2, b2, x, out);
}

// round 16
// speedup vs baseline: 1.2127x; 1.2127x over previous
#include <cuda_runtime.h>
#include <cuda_bf16.h>

// Problem constants
#define BATCH 128
#define BINS 128
#define HW 262144               // 512*512 elements per batch (C=1)
#define TOTAL (BATCH * HW)      // 33554432
#define HIST_BPB 16             // histogram blocks per batch
#define HIST_THREADS 256
#define CHUNK (HW / HIST_BPB)   // 16384 elements per hist block

// Scratch (device globals: no allocations allowed)
__device__ float g_part[HIST_BPB * BATCH * BINS];   // [part][batch][bin]
__device__ float g_w[BATCH];
__device__ unsigned int g_cnt[BATCH];   // monotonic arrival counters (each launch
                                        // adds exactly HIST_BPB per batch; the
                                        // mod-16 test is replay/graph safe)

// 32-byte (8-float) global load with L2 evict_last policy (sm_103a requires
// .v8.b32/.v4.b64 for this modifier).
struct F8 { float f[8]; };
static __device__ __forceinline__ F8 ldg32_evict_last(const void* p) {
    unsigned long long a, b, c, d;
    asm volatile("ld.global.L2::evict_last.v4.b64 {%0,%1,%2,%3}, [%4];"
                 : "=l"(a), "=l"(b), "=l"(c), "=l"(d)
                 : "l"(p));
    F8 r;
    r.f[0] = __uint_as_float((unsigned)(a));  r.f[1] = __uint_as_float((unsigned)(a >> 32));
    r.f[2] = __uint_as_float((unsigned)(b));  r.f[3] = __uint_as_float((unsigned)(b >> 32));
    r.f[4] = __uint_as_float((unsigned)(c));  r.f[5] = __uint_as_float((unsigned)(c >> 32));
    r.f[6] = __uint_as_float((unsigned)(d));  r.f[7] = __uint_as_float((unsigned)(d >> 32));
    return r;
}

// ---------------------------------------------------------------------------
// Kernel 1: per-batch histogram (R10 structure: 29.5us) + last-block MLP.
// 256 threads/block, per-thread private UINT8 counters, 32 KB smem,
// conflict-free layout (word bank = t&31, independent of bin).
// After storing its partial, the LAST arriving block of each batch (atomic
// generation counter) computes w[batch] in-place: no separate mlp kernel.
// ---------------------------------------------------------------------------
__global__ void __launch_bounds__(HIST_THREADS) hist_kernel(const float* __restrict__ x,
                                                            const float* __restrict__ W1,
                                                            const float* __restrict__ b1,
                                                            const float* __restrict__ W2,
                                                            const float* __restrict__ b2) {
    __shared__ unsigned char sh[BINS * 256];             // 32 KB
    __shared__ float sh_h[4][16];
    __shared__ unsigned int s_last;
    unsigned int* sh32 = reinterpret_cast<unsigned int*>(sh);

    const int t = threadIdx.x;

    // zero: 8192 words / 256 threads = 32 each, bank = t&31: conflict-free
    #pragma unroll
    for (int i = 0; i < 32; i++)
        sh32[i * 256 + t] = 0u;
    __syncthreads();

    const int batch = blockIdx.x >> 4;              // / HIST_BPB
    const int part  = blockIdx.x & (HIST_BPB - 1);
    const int lane_off = (t & 31) * 4 + ((t >> 5) & 3) + (t >> 7) * 128;

    const char* xp = reinterpret_cast<const char*>(x)
                   + ((size_t)batch * HW + (size_t)part * CHUNK) * 4;

    // CHUNK/8 = 2048 8-float groups per block, 256 threads -> 8 iterations
    #pragma unroll 8
    for (int i = t; i < CHUNK / 8; i += HIST_THREADS) {
        F8 v = ldg32_evict_last(xp + (size_t)i * 32);
        #pragma unroll
        for (int e = 0; e < 8; e++) {
            float g = v.f[e] * 128.0f;               // exact (x * 2^7)
            int bin = min(__float2int_rd(g), BINS - 1);
            if (g >= 0.0f && g <= 128.0f) sh[bin * 256 + lane_off]++;
        }
    }
    __syncthreads();

    // Reduce: thread t (t<128) sums bin t's 256 counters = 64 words x 4 bytes
    // (dp4a). Rotated read -> conflict-free. Store partial to global.
    if (t < BINS) {
        unsigned int s = 0;
        #pragma unroll
        for (int i = 0; i < 64; i++) {
            int j = (t + i) & 63;
            s = __dp4a(sh32[t * 64 + j], 0x01010101u, s);
        }
        g_part[(part * BATCH + batch) * BINS + t] = (float)s;
    }

    // ---- last-block-per-batch arbitration (threadFenceReduction pattern) ----
    __threadfence();           // release g_part stores (all threads)
    __syncthreads();           // order fences before thread 0's atomic
    if (t == 0) {
        unsigned int old = atomicAdd(&g_cnt[batch], 1u);
        s_last = ((old & (HIST_BPB - 1)) == (HIST_BPB - 1)) ? 1u : 0u;
    }
    __syncthreads();
    if (!s_last) return;

    // ---- MLP for this batch (one block per batch per launch reaches here) ----
    const int lane = t & 31;
    const int warp = t >> 5;
    float hp[16];
    if (t < BINS) {
        float c = 0.0f;
        #pragma unroll
        for (int p = 0; p < HIST_BPB; p++)
            c += g_part[(p * BATCH + batch) * BINS + t];
        #pragma unroll
        for (int j = 0; j < 16; j++)
            hp[j] = c * W1[t * 16 + j];
    } else {
        #pragma unroll
        for (int j = 0; j < 16; j++) hp[j] = 0.0f;
    }
    if (warp < 4) {
        #pragma unroll
        for (int j = 0; j < 16; j++) {
            #pragma unroll
            for (int off = 16; off >= 1; off >>= 1)
                hp[j] += __shfl_xor_sync(0xFFFFFFFFu, hp[j], off);
        }
        if (lane == 0) {
            #pragma unroll
            for (int j = 0; j < 16; j++)
                sh_h[warp][j] = hp[j];
        }
    }
    __syncthreads();
    if (t < 32) {
        float v = 0.0f;
        if (t < 16) {
            float h = sh_h[0][t] + sh_h[1][t] + sh_h[2][t] + sh_h[3][t] + b1[t];
            v = fmaxf(h, 0.0f) * W2[t];
        }
        #pragma unroll
        for (int off = 8; off >= 1; off >>= 1)
            v += __shfl_xor_sync(0xFFFFFFFFu, v, off);
        if (t == 0)
            g_w[batch] = v + b2[0];
    }
}

// ---------------------------------------------------------------------------
// Kernel 2: out = x * w[batch]. EXACT R10 version (measured ~35us):
// 32768 blocks (full occupancy), reversed block order (hot L2 tail first),
// __ldcs read (dead after), __stcs write (don't pollute L2).
// ---------------------------------------------------------------------------
__global__ void __launch_bounds__(256) scale_kernel(const float* __restrict__ x,
                                                    float* __restrict__ out) {
    size_t vi = (size_t)(gridDim.x - 1 - blockIdx.x) * blockDim.x + threadIdx.x;
    float w = g_w[vi >> 16];
    float4 v = __ldcs(reinterpret_cast<const float4*>(x) + vi);
    v.x *= w; v.y *= w; v.z *= w; v.w *= w;
    __stcs(reinterpret_cast<float4*>(out) + vi, v);
}

// ---------------------------------------------------------------------------
// Launch: two kernels; MLP rides inside hist's last block per batch.
// ---------------------------------------------------------------------------
extern "C" void kernel_launch(void* const* d_in, const int* in_sizes, int n_in,
                              void* d_out, int out_size) {
    const float* x  = (const float*)d_in[0];
    const float* W1 = (const float*)d_in[1];
    const float* b1 = (const float*)d_in[2];
    const float* W2 = (const float*)d_in[3];
    const float* b2 = (const float*)d_in[4];
    float* out = (float*)d_out;

    hist_kernel<<<BATCH * HIST_BPB, HIST_THREADS>>>(x, W1, b1, W2, b2);
    scale_kernel<<<(TOTAL / 4) / 256, 256>>>(x, out);
}